// round 7
// baseline (speedup 1.0000x reference)
#include <cuda_runtime.h>
#include <cstdint>

// CTC batch cost (Keras ctc_batch_cost, full lengths).
// B=64, T=2048, C=128 (blank=127), L=256, S=2L+1=513.
//
// R7 = R6 with the cluster-credit deadlock fixed (credit depth 1: rank0 at
// exchange m waits rev phase m-1, parity (m&1)^1 -- depth-2 parity waits are
// ambiguous and deadlock).
//
// Design: wavefront-skewed warps. 2-CTA cluster per batch (128 CTAs); 9
// warps/CTA; per-step sync is PAIRWISE named-barrier rendezvous (ids 1..8,
// count 64), so warps pipeline across time steps and run at the MUFU floor
// (~72 cyc/step/SM) instead of the serial latency chain.
// lp = log2(y_pred+eps) precomputed into a __device__ scratch by a coalesced
// pre-kernel; each thread LDG-prefetches its own lp[cls] 8 steps ahead.
// Cluster halo refresh every 16 steps via boundary-warp-only mbarriers.
// y_true is int32.

#define CTC_B 64
#define CTC_T 2048
#define CTC_C 128
#define CTC_L 256
#define NEGF (-1e30f)
#define EPSF (1e-7f)
#define LN2F (0.69314718055994530942f)
#define NTHR 288

__device__ float g_lp[(size_t)CTC_B * CTC_T * CTC_C];   // 64MB scratch

__device__ __forceinline__ float ex2f_(float x) {
    float r; asm("ex2.approx.ftz.f32 %0, %1;" : "=f"(r) : "f"(x)); return r;
}
__device__ __forceinline__ float lg2f_(float x) {
    float r; asm("lg2.approx.ftz.f32 %0, %1;" : "=f"(r) : "f"(x)); return r;
}
__device__ __forceinline__ uint32_t smem_u32_(const void* p) {
    uint32_t a;
    asm("{ .reg .u64 t; cvta.to.shared.u64 t, %1; cvt.u32.u64 %0, t; }"
        : "=r"(a) : "l"(p));
    return a;
}

// ---- pre-kernel: g_lp = log2(y_pred + eps), coalesced float4 ----
__global__ void lp_precompute_kernel(const float* __restrict__ y) {
    int i = blockIdx.x * blockDim.x + threadIdx.x;   // exact-size launch
    const float4* y4 = (const float4*)y;
    float4* o4 = (float4*)g_lp;
    float4 v = y4[i];
    float4 r;
    r.x = lg2f_(v.x + EPSF);
    r.y = lg2f_(v.y + EPSF);
    r.z = lg2f_(v.z + EPSF);
    r.w = lg2f_(v.w + EPSF);
    o4[i] = r;
}

// mbarrier parity wait (acquire, cluster scope), bounded spin: if the
// protocol is correct the bound (>~4M iters) is never reached; if not, we
// finish with a wrong answer instead of hanging the bench.
#define MBWAIT(addr, par) do {                                                 \
        uint32_t _d; int _n = 0;                                               \
        do {                                                                   \
            asm volatile("{\n\t.reg .pred p;\n\t"                              \
                "mbarrier.try_wait.parity.acquire.cluster.shared::cta.b64 "    \
                "p, [%1], %2, 0x989680;\n\t"                                   \
                "selp.b32 %0, 1, 0, p;\n\t}"                                   \
                : "=r"(_d) : "r"((uint32_t)(addr)), "r"((uint32_t)(par))       \
                : "memory");                                                   \
        } while (!_d && ++_n < (1 << 22));                                     \
    } while (0)

__global__ __launch_bounds__(NTHR, 1) __cluster_dims__(2, 1, 1)
void ctc_forward_kernel(const int* __restrict__ y_true,
                        const float* __restrict__ y_pred,
                        float* __restrict__ out) {
    __shared__ float s_alpha[2][280];        // local state idx + 2; dummy @278
    __shared__ float s_mail[2][32];          // cluster halo mailbox (rank1)
    __shared__ alignas(8) uint64_t s_fwd;    // data-ready mbar (rank1 side)
    __shared__ alignas(8) uint64_t s_rev;    // mailbox-credit mbar (rank0 side)

    const int tid  = threadIdx.x;
    const int lane = tid & 31;
    const int wid  = tid >> 5;
    uint32_t rank;
    asm("mov.u32 %0, %%cluster_ctarank;" : "=r"(rank));
    const int b = blockIdx.x >> 1;

    const int*   lab = y_true + b * CTC_L;
    const float* Y   = y_pred + (size_t)b * CTC_T * CTC_C;
    const float* LP  = g_lp   + (size_t)b * CTC_T * CTC_C;

    // rank0 owns states [0,272); rank1 computes [240,513) (halo [240,272))
    const int  s      = rank ? (240 + tid) : tid;
    const bool active = rank ? (tid < 273) : (tid < 272);
    const int  ai     = active ? tid + 2 : 278;

    int cls = CTC_C - 1, skip = 0;
    if (active && (s & 1)) {
        int i = s >> 1;
        cls  = lab[i] & 127;
        skip = (s >= 3 && cls != (lab[i - 1] & 127)) ? 1 : 0;
    }

    // ---- init ----
    for (int i = tid; i < 280; i += NTHR) {
        s_alpha[0][i] = NEGF;
        s_alpha[1][i] = NEGF;
    }
    if (tid == 0) {
        uint32_t f = smem_u32_(&s_fwd), r = smem_u32_(&s_rev);
        asm volatile("mbarrier.init.shared.b64 [%0], 64;" :: "r"(f) : "memory");
        asm volatile("mbarrier.init.shared.b64 [%0], 32;" :: "r"(r) : "memory");
    }
    asm volatile("bar.sync 0, %0;" :: "r"(NTHR) : "memory");

    // alpha0: state0 = blank@t0, state1 = label0@t0 (rank0)
    if (rank == 0 && tid == 0) s_alpha[0][2] = lg2f_(Y[CTC_C - 1] + EPSF);
    if (rank == 0 && tid == 1) s_alpha[0][3] = lg2f_(Y[lab[0] & 127] + EPSF);

    // remote addresses
    uint32_t r_mail0 = 0, r_mail1 = 0, r_fwd = 0, r_rev = 0;
    {
        const int one = 1, zero = 0;
        if (rank == 0) {
            int mi = (tid >= 240 && tid < 272) ? (tid - 240) : 0;
            uint32_t l0 = smem_u32_(&s_mail[0][mi]);
            uint32_t l1 = smem_u32_(&s_mail[1][mi]);
            uint32_t lf = smem_u32_(&s_fwd);
            asm("mapa.shared::cluster.u32 %0, %1, %2;" : "=r"(r_mail0) : "r"(l0), "r"(one));
            asm("mapa.shared::cluster.u32 %0, %1, %2;" : "=r"(r_mail1) : "r"(l1), "r"(one));
            asm("mapa.shared::cluster.u32 %0, %1, %2;" : "=r"(r_fwd)   : "r"(lf), "r"(one));
        } else {
            uint32_t lr = smem_u32_(&s_rev);
            asm("mapa.shared::cluster.u32 %0, %1, %2;" : "=r"(r_rev) : "r"(lr), "r"(zero));
        }
    }

    // lp register fifo: rows 1..8 (per-thread gather, one-time)
    float q[8];
#pragma unroll
    for (int j = 0; j < 8; j++) q[j] = LP[(size_t)(1 + j) * CTC_C + cls];

    asm volatile("bar.sync 0, %0;" :: "r"(NTHR) : "memory");
    float cur = s_alpha[0][ai];

    // mbarriers (and alpha0) visible cluster-wide before any remote op
    asm volatile("barrier.cluster.arrive.aligned;" ::: "memory");
    asm volatile("barrier.cluster.wait.aligned;"   ::: "memory");

    const uint32_t l_fwd = smem_u32_(&s_fwd);
    const uint32_t l_rev = smem_u32_(&s_rev);

#define LPLOAD(tt, J) do {                                                     \
        int rr_ = (tt) + 8; if (rr_ > CTC_T - 1) rr_ = CTC_T - 1;              \
        q[J] = LP[(size_t)rr_ * CTC_C + cls];                                  \
    } while (0)

#define PAIRBARS() do {                                                        \
        if (wid > 0) asm volatile("bar.sync %0, 64;" :: "r"(wid) : "memory");  \
        if (wid < 8) asm volatile("bar.sync %0, 64;" :: "r"(wid + 1) : "memory"); \
    } while (0)

#define COMPUTE(P, J) do {                                                     \
        float bv = s_alpha[1 - (P)][ai - 1];                                   \
        float cs = s_alpha[1 - (P)][ai - 2];                                   \
        float cv = skip ? cs : NEGF;                                           \
        float m  = fmaxf(cur, fmaxf(bv, cv));                                  \
        float sum = (ex2f_(cur - m) + ex2f_(bv - m)) + ex2f_(cv - m);          \
        cur = (m + q[J]) + lg2f_(sum);                                         \
        s_alpha[(P)][ai] = cur;                                                \
    } while (0)

#define STEP(tt, P, J) do {                                                    \
        COMPUTE(P, J);                                                         \
        LPLOAD(tt, J);                                                         \
        PAIRBARS();                                                            \
    } while (0)

    // exchange step: tt multiple of 16 (even -> P=0), round m_ = tt/16 - 1.
    // Credit depth 1: rank0 at exchange m_ waits rev phase m_-1 (parity
    // (m_&1)^1). Pending rev then is m_-1 (block) or m_ (pass) -- 1-bit
    // parity is unambiguous on a 2-phase window. (Depth-2 deadlocks: R6.)
#define STEPX(tt, J) do {                                                      \
        int m_ = ((tt) >> 4) - 1;                                              \
        if (rank == 0 && wid >= 7 && m_ >= 1) MBWAIT(l_rev, (m_ & 1) ^ 1);     \
        COMPUTE(0, J);                                                         \
        if (rank == 0 && wid >= 7) {                                           \
            if (tid >= 240 && tid < 272) {                                     \
                uint32_t ra = (m_ & 1) ? r_mail1 : r_mail0;                    \
                asm volatile("st.shared::cluster.f32 [%0], %1;"                \
                             :: "r"(ra), "f"(cur) : "memory");                 \
            }                                                                  \
            asm volatile(                                                      \
              "mbarrier.arrive.release.cluster.shared::cluster.b64 _, [%0];"   \
              :: "r"(r_fwd) : "memory");                                       \
        }                                                                      \
        if (rank == 1 && wid == 0) {                                           \
            MBWAIT(l_fwd, m_ & 1);                                             \
            cur = s_mail[m_ & 1][lane];                                        \
            s_alpha[0][ai] = cur;                                              \
            asm volatile(                                                      \
              "mbarrier.arrive.release.cluster.shared::cluster.b64 _, [%0];"   \
              :: "r"(r_rev) : "memory");                                       \
        }                                                                      \
        LPLOAD(tt, J);                                                         \
        PAIRBARS();                                                            \
    } while (0)

    // main: groups of 8 steps; t0 = 1,9,...,2033; exchange at t==16m (g odd)
    for (int g = 0; g < 255; g++) {
        int t0 = 1 + 8 * g;
        STEP(t0 + 0, 1, 0);
        STEP(t0 + 1, 0, 1);
        STEP(t0 + 2, 1, 2);
        STEP(t0 + 3, 0, 3);
        STEP(t0 + 4, 1, 4);
        STEP(t0 + 5, 0, 5);
        STEP(t0 + 6, 1, 6);
        if (g & 1) STEPX(t0 + 7, 7);
        else       STEP(t0 + 7, 0, 7);
    }
    // tail: t = 2041..2047
    STEP(2041, 1, 0);
    STEP(2042, 0, 1);
    STEP(2043, 1, 2);
    STEP(2044, 0, 3);
    STEP(2045, 1, 4);
    STEP(2046, 0, 5);
    STEP(2047, 1, 6);

#undef STEP
#undef STEPX
#undef COMPUTE
#undef PAIRBARS
#undef LPLOAD

    asm volatile("bar.sync 0, %0;" :: "r"(NTHR) : "memory");

    // final alpha (t=2047, row 1): rank1 local idx 271->state511, 272->state512
    if (rank == 1 && tid == 0) {
        float a = s_alpha[1][274];   // state 512
        float c = s_alpha[1][273];   // state 511
        float m = fmaxf(a, c);
        float l2 = m + lg2f_(ex2f_(a - m) + ex2f_(c - m));
        out[b] = -l2 * LN2F;
    }

    // keep both CTAs alive until all remote ops landed
    asm volatile("barrier.cluster.arrive.aligned;" ::: "memory");
    asm volatile("barrier.cluster.wait.aligned;"   ::: "memory");
}

extern "C" void kernel_launch(void* const* d_in, const int* in_sizes, int n_in,
                              void* d_out, int out_size) {
    const int*   y_true;
    const float* y_pred;
    if (in_sizes[0] == CTC_B * CTC_L) {
        y_true = (const int*)d_in[0];
        y_pred = (const float*)d_in[1];
    } else {
        y_true = (const int*)d_in[1];
        y_pred = (const float*)d_in[0];
    }
    float* out = (float*)d_out;

    // 1) precompute log2(y_pred+eps): B*T*C/4 float4 elems, exact-size launch
    const int n4 = CTC_B * CTC_T * CTC_C / 4;   // 4,194,304
    lp_precompute_kernel<<<n4 / 512, 512>>>(y_pred);

    // 2) skewed forward recurrence
    ctc_forward_kernel<<<2 * CTC_B, NTHR>>>(y_true, y_pred, out);
}

// round 13
// speedup vs baseline: 1.4374x; 1.4374x over previous
#include <cuda_runtime.h>
#include <cstdint>

// CTC batch cost (Keras ctc_batch_cost, full lengths).
// B=64, T=2048, C=128 (blank=127), L=256, S=2L+1=513.
//
// R11 = R4 (proven, 248us) with three step-level cuts:
//  1. own alpha carried in a register (2 LDS/step instead of 3)
//  2. lse3 with 2 EX2 (max term == 1 exactly): sum = 1 + ex2(p-M) + ex2(q-M)
//  3. per-thread lp register fifo (LDG Y[t+8,cls] -> off-path LG2);
//     no shared lp, no producer warps, uniform barrier arrival
// Everything else (2-CTA cluster per batch, rank0 owns [0,272), rank1
// computes [240,513) with 32-state halo refreshed every 16 steps via
// st.shared::cluster + full cluster barrier) is identical to R4.
// y_true is int32.

#define CTC_B 64
#define CTC_T 2048
#define CTC_C 128
#define CTC_L 256
#define NEGF (-1e30f)
#define EPSF (1e-7f)
#define LN2F (0.69314718055994530942f)

#define SPLIT   272     // rank0 owns [0,272)
#define HALO    32      // rank1 redundant states [240,272)
#define NTHR    288     // 9 warps
#define ALPHA_N 280     // 2 left pads + states + dummy slot @278

__device__ __forceinline__ float ex2f_(float x) {
    float r; asm("ex2.approx.ftz.f32 %0, %1;" : "=f"(r) : "f"(x)); return r;
}
__device__ __forceinline__ float lg2f_(float x) {
    float r; asm("lg2.approx.ftz.f32 %0, %1;" : "=f"(r) : "f"(x)); return r;
}
__device__ __forceinline__ uint32_t smem_u32_(const void* p) {
    uint32_t a;
    asm("{ .reg .u64 t; cvta.to.shared.u64 t, %1; cvt.u32.u64 %0, t; }"
        : "=r"(a) : "l"(p));
    return a;
}

__global__ __launch_bounds__(NTHR, 1) __cluster_dims__(2, 1, 1)
void ctc_forward_kernel(const int* __restrict__ y_true,
                        const float* __restrict__ y_pred,
                        float* __restrict__ out) {
    __shared__ float s_alpha[2][ALPHA_N];
    __shared__ float s_halo[2][HALO];     // cluster mailbox (rank1 side)

    const int tid = threadIdx.x;
    uint32_t rank;
    asm("mov.u32 %0, %%cluster_ctarank;" : "=r"(rank));
    const int b = blockIdx.x >> 1;

    const int*   lab = y_true + b * CTC_L;
    const float* Y   = y_pred + (size_t)b * CTC_T * CTC_C;

    // rank0 owns [0,272); rank1 computes [240,513) (halo [240,272))
    const int  s      = rank ? (240 + tid) : tid;
    const bool active = rank ? (tid < 273) : (tid < SPLIT);
    const int  ai     = active ? tid + 2 : 278;

    int cls = CTC_C - 1, skip = 0;
    if (active && (s & 1)) {
        int i = s >> 1;
        cls  = lab[i] & 127;
        skip = (s >= 3 && cls != (lab[i - 1] & 127)) ? 1 : 0;
    }
    const float* Yc = Y + cls;

    // ---- init alpha buffers to NEG ----
    for (int i = tid; i < ALPHA_N; i += NTHR) {
        s_alpha[0][i] = NEGF;
        s_alpha[1][i] = NEGF;
    }
    __syncthreads();

    // alpha0: state0 = blank@t0, state1 = label0@t0 (rank0 only)
    if (rank == 0 && tid == 0) s_alpha[0][2] = lg2f_(Y[CTC_C - 1] + EPSF);
    if (rank == 0 && tid == 1) s_alpha[0][3] = lg2f_(Y[lab[0] & 127] + EPSF);

    // remote mailbox addresses for rank0 boundary senders (states 240..271)
    uint32_t rh0 = 0, rh1 = 0;
    if (rank == 0 && tid >= 240 && tid < SPLIT) {
        uint32_t l0 = smem_u32_(&s_halo[0][tid - 240]);
        uint32_t l1 = smem_u32_(&s_halo[1][tid - 240]);
        asm("mapa.shared::cluster.u32 %0, %1, %2;" : "=r"(rh0) : "r"(l0), "r"(1));
        asm("mapa.shared::cluster.u32 %0, %1, %2;" : "=r"(rh1) : "r"(l1), "r"(1));
    }

    // lp register fifo for frames 1..8: lg2(y+eps), per-thread class column
    float q[8];
#pragma unroll
    for (int j = 0; j < 8; j++) q[j] = lg2f_(Yc[(1 + j) << 7] + EPSF);

    __syncthreads();
    float cur = s_alpha[0][ai];

#define QLOAD(tt, J) do {                                                      \
        int rr_ = (tt) + 8; if (rr_ > CTC_T - 1) rr_ = CTC_T - 1;              \
        q[J] = lg2f_(Yc[rr_ << 7] + EPSF);                                     \
    } while (0)

    // 2-EX2 lse3: M = max(cur,bv,cv); others p=min(cur,bv), q2=min(max(cur,bv),cv)
#define COMPUTE(P, J) do {                                                     \
        float bv = s_alpha[1 - (P)][ai - 1];                                   \
        float cv = skip ? s_alpha[1 - (P)][ai - 2] : NEGF;                     \
        float mx = fmaxf(cur, bv);                                             \
        float mn = fminf(cur, bv);                                             \
        float M  = fmaxf(mx, cv);                                              \
        float q2 = fminf(mx, cv);                                              \
        float sum = 1.0f + ex2f_(mn - M) + ex2f_(q2 - M);                      \
        cur = (M + q[J]) + lg2f_(sum);                                         \
        s_alpha[(P)][ai] = cur;                                                \
    } while (0)

#define STEP(tt, P, J) do {                                                    \
        COMPUTE(P, J);                                                         \
        QLOAD(tt, J);                                                          \
        __syncthreads();                                                       \
    } while (0)

    // main: groups of 8 steps, tt = 8g+1..8g+8, g = 0..254 (tt 1..2040);
    // cluster halo exchange at tt % 16 == 0 (g odd), exactly as R4.
    for (int g = 0; g < 255; g++) {
        int t0 = 8 * g + 1;
        STEP(t0 + 0, 1, 0);
        STEP(t0 + 1, 0, 1);
        STEP(t0 + 2, 1, 2);
        STEP(t0 + 3, 0, 3);
        STEP(t0 + 4, 1, 4);
        STEP(t0 + 5, 0, 5);
        STEP(t0 + 6, 1, 6);
        STEP(t0 + 7, 0, 7);

        if (g & 1) {
            // alpha at time t0+7 (= 16m) just written to buffer 0; cur holds it
            int buf = ((t0 + 7) >> 4) & 1;
            if (rank == 0 && tid >= 240 && tid < SPLIT) {
                uint32_t ra = buf ? rh1 : rh0;
                asm volatile("st.shared::cluster.f32 [%0], %1;"
                             :: "r"(ra), "f"(cur) : "memory");
            }
            asm volatile("barrier.cluster.arrive.aligned;" ::: "memory");
            asm volatile("barrier.cluster.wait.aligned;"   ::: "memory");
            if (rank == 1) {
                if (tid < HALO) {
                    cur = s_halo[buf][tid];          // refresh register copy
                    s_alpha[0][tid + 2] = cur;       // and shared copy
                }
                __syncthreads();
            }
        }
    }
    // tail: tt = 2041..2047
    STEP(2041, 1, 0);
    STEP(2042, 0, 1);
    STEP(2043, 1, 2);
    STEP(2044, 0, 3);
    STEP(2045, 1, 4);
    STEP(2046, 0, 5);
    STEP(2047, 1, 6);

#undef STEP
#undef COMPUTE
#undef QLOAD

    // final alpha (t=2047) in buffer 1: rank1 idx 273 -> state 511, 274 -> 512
    if (rank == 1 && tid == 0) {
        float a = s_alpha[1][274];
        float c = s_alpha[1][273];
        float m = fmaxf(a, c);
        float l2 = m + lg2f_(ex2f_(a - m) + ex2f_(c - m));
        out[b] = -l2 * LN2F;
    }

    // keep both CTAs alive until all remote ops landed
    asm volatile("barrier.cluster.arrive.aligned;" ::: "memory");
    asm volatile("barrier.cluster.wait.aligned;"   ::: "memory");
}

extern "C" void kernel_launch(void* const* d_in, const int* in_sizes, int n_in,
                              void* d_out, int out_size) {
    const int*   y_true;
    const float* y_pred;
    if (in_sizes[0] == CTC_B * CTC_L) {
        y_true = (const int*)d_in[0];
        y_pred = (const float*)d_in[1];
    } else {
        y_true = (const int*)d_in[1];
        y_pred = (const float*)d_in[0];
    }
    float* out = (float*)d_out;

    ctc_forward_kernel<<<2 * CTC_B, NTHR>>>(y_true, y_pred, out);
}

// round 15
// speedup vs baseline: 1.5774x; 1.0974x over previous
#include <cuda_runtime.h>
#include <cstdint>

// CTC batch cost (Keras ctc_batch_cost, full lengths).
// B=64, T=2048, C=128 (blank=127), L=256, S=2L+1=513.
//
// R14: FOUR time-steps per __syncthreads via overlapped warps.
// Warp w lanes k hold states l = 26w - 6 + k (6-state overlap with left
// warp). Period: load alpha_t[l], [l-1], [l-2] from shared -> step t+1 exact
// for ALL lanes; steps t+2..t+4 use shfl_up neighbors; lanes 0..5 decay
// 2 states/step; lanes >= 6 (net 26 states/warp) stay exact -> they write
// alpha_{t+4} to the other shared buffer. 1 barrier + 1 shared round trip
// per 4 steps. 11 warps cover 273+ states.
// lp tables (log2(y+eps), 4 frames) produced per period by threads 0..127
// into a parity double buffer (in the barrier shadow), y LDG-prefetched 2
// periods ahead. 2-CTA cluster per batch, 32-state halo refreshed every 16
// steps (= every 4th period) via R11's proven st.shared::cluster + full
// cluster-barrier protocol. y_true is int32.

#define CTC_B 64
#define CTC_T 2048
#define CTC_C 128
#define CTC_L 256
#define NEGF (-1e30f)
#define EPSF (1e-7f)
#define LN2F (0.69314718055994530942f)

#define NTHR  352      // 11 warps
#define NETW  26       // net states per warp
#define OVL   6        // overlapped (decaying) lanes per warp
#define PADL  8        // left NEG pads in alpha rows
#define ANROW 304      // PADL + max l (285) + margin

__device__ __forceinline__ float ex2f_(float x) {
    float r; asm("ex2.approx.ftz.f32 %0, %1;" : "=f"(r) : "f"(x)); return r;
}
__device__ __forceinline__ float lg2f_(float x) {
    float r; asm("lg2.approx.ftz.f32 %0, %1;" : "=f"(r) : "f"(x)); return r;
}
__device__ __forceinline__ uint32_t smem_u32_(const void* p) {
    uint32_t a;
    asm("{ .reg .u64 t; cvta.to.shared.u64 t, %1; cvt.u32.u64 %0, t; }"
        : "=r"(a) : "l"(p));
    return a;
}

__global__ __launch_bounds__(NTHR, 1) __cluster_dims__(2, 1, 1)
void ctc_forward_kernel(const int* __restrict__ y_true,
                        const float* __restrict__ y_pred,
                        float* __restrict__ out) {
    __shared__ float s_A[2][ANROW];          // alpha, period-parity buffered
    __shared__ float s_lpt[2][4][CTC_C];     // lp tables, period-parity buffered
    __shared__ float s_mail[2][32];          // cluster halo mailbox (rank1)

    const int tid  = threadIdx.x;
    const int lane = tid & 31;
    const int wid  = tid >> 5;
    uint32_t rank;
    asm("mov.u32 %0, %%cluster_ctarank;" : "=r"(rank));
    const int b = blockIdx.x >> 1;

    const int*   lab = y_true + b * CTC_L;
    const float* Y   = y_pred + (size_t)b * CTC_T * CTC_C;

    // lane -> state mapping (rank0 owns [0,272); rank1 computes [240,513))
    const int l  = NETW * wid - OVL + lane;   // -6 .. 285
    const int li = l + PADL;                  // 2 .. 293 (reads down to li-2=0)
    const int s  = rank ? (l + 240) : l;

    int cls = CTC_C - 1, skip = 0;
    if (s >= 1 && (s & 1)) {
        int i = s >> 1; if (i > CTC_L - 1) i = CTC_L - 1;   // clamp overshoot lanes
        cls  = lab[i] & 127;
        skip = (s >= 3 && cls != (lab[i - 1] & 127)) ? 1 : 0;
    }

    // ---- init alpha buffers to NEG ----
    for (int i = tid; i < ANROW; i += NTHR) {
        s_A[0][i] = NEGF;
        s_A[1][i] = NEGF;
    }
    __syncthreads();

    // alpha0: state0 = blank@t0, state1 = label0@t0 (rank0 only)
    if (rank == 0 && tid == 0) s_A[0][PADL + 0] = lg2f_(Y[CTC_C - 1] + EPSF);
    if (rank == 0 && tid == 1) s_A[0][PADL + 1] = lg2f_(Y[lab[0] & 127] + EPSF);

    // remote mailbox addresses for rank0 boundary senders (states 240..271)
    uint32_t rh0 = 0, rh1 = 0;
    if (rank == 0 && tid >= 240 && tid < 272) {
        uint32_t a0 = smem_u32_(&s_mail[0][tid - 240]);
        uint32_t a1 = smem_u32_(&s_mail[1][tid - 240]);
        asm("mapa.shared::cluster.u32 %0, %1, %2;" : "=r"(rh0) : "r"(a0), "r"(1));
        asm("mapa.shared::cluster.u32 %0, %1, %2;" : "=r"(rh1) : "r"(a1), "r"(1));
    }

    // producer prologue: table for period 0 (frames 1..4); prefetch y for
    // productions during periods 0 (frames 5..8) and 1 (frames 9..12)
    float ya0 = 0.f, ya1 = 0.f, ya2 = 0.f, ya3 = 0.f;
    float yb0 = 0.f, yb1 = 0.f, yb2 = 0.f, yb3 = 0.f;
    const float* Yt = Y + tid;
    if (tid < CTC_C) {
        s_lpt[0][0][tid] = lg2f_(Yt[1 << 7] + EPSF);
        s_lpt[0][1][tid] = lg2f_(Yt[2 << 7] + EPSF);
        s_lpt[0][2][tid] = lg2f_(Yt[3 << 7] + EPSF);
        s_lpt[0][3][tid] = lg2f_(Yt[4 << 7] + EPSF);
        ya0 = Yt[5 << 7];  ya1 = Yt[6 << 7];  ya2 = Yt[7 << 7];  ya3 = Yt[8 << 7];
        yb0 = Yt[9 << 7];  yb1 = Yt[10 << 7]; yb2 = Yt[11 << 7]; yb3 = Yt[12 << 7];
    }
    __syncthreads();

    // 2-EX2 lse3 + add lp: cur = lse3(cur, b1v, skip?b2v:NEG) + qv
#define SUB(qv) do {                                                           \
        float cv = skip ? b2v : NEGF;                                          \
        float mx = fmaxf(cur, b1v);                                            \
        float mn = fminf(cur, b1v);                                            \
        float M  = fmaxf(mx, cv);                                              \
        float m2 = fminf(mx, cv);                                              \
        float sum = 1.0f + ex2f_(mn - M) + ex2f_(m2 - M);                      \
        cur = (M + (qv)) + lg2f_(sum);                                         \
    } while (0)

    // one 4-step period; H = p&1 literal; Y0..Y3 = this-parity y prefetch regs
#define PERIOD(p, H, Y0, Y1, Y2, Y3) do {                                      \
        const float* __restrict__ Ar = s_A[(H)];                               \
        float*       __restrict__ Aw = s_A[1 - (H)];                           \
        float q0 = s_lpt[(H)][0][cls], q1 = s_lpt[(H)][1][cls];                \
        float q2 = s_lpt[(H)][2][cls], q3 = s_lpt[(H)][3][cls];                \
        float cur = Ar[li];                                                    \
        float b1v = Ar[li - 1];                                                \
        float b2v = Ar[li - 2];                                                \
        SUB(q0);                                                               \
        b1v = __shfl_up_sync(0xffffffffu, cur, 1);                             \
        b2v = __shfl_up_sync(0xffffffffu, cur, 2);                             \
        SUB(q1);                                                               \
        b1v = __shfl_up_sync(0xffffffffu, cur, 1);                             \
        b2v = __shfl_up_sync(0xffffffffu, cur, 2);                             \
        SUB(q2);                                                               \
        b1v = __shfl_up_sync(0xffffffffu, cur, 1);                             \
        b2v = __shfl_up_sync(0xffffffffu, cur, 2);                             \
        SUB(q3);                                                               \
        if (lane >= OVL) Aw[li] = cur;                                         \
        if (tid < CTC_C) {                                                     \
            s_lpt[1 - (H)][0][tid] = lg2f_((Y0) + EPSF);                       \
            s_lpt[1 - (H)][1][tid] = lg2f_((Y1) + EPSF);                       \
            s_lpt[1 - (H)][2][tid] = lg2f_((Y2) + EPSF);                       \
            s_lpt[1 - (H)][3][tid] = lg2f_((Y3) + EPSF);                       \
            int f0 = 4 * (p) + 13, f1 = f0 + 1, f2 = f0 + 2, f3 = f0 + 3;      \
            if (f0 > 2047) f0 = 2047;  if (f1 > 2047) f1 = 2047;               \
            if (f2 > 2047) f2 = 2047;  if (f3 > 2047) f3 = 2047;               \
            (Y0) = Yt[f0 << 7]; (Y1) = Yt[f1 << 7];                            \
            (Y2) = Yt[f2 << 7]; (Y3) = Yt[f3 << 7];                            \
        }                                                                      \
        __syncthreads();                                                       \
    } while (0)

    // cluster halo exchange after periods p%4==3 (t_end = 4p+4 = 16m)
#define XCHG(p) do { if (((p) & 3) == 3) {                                     \
        int m_   = ((p) + 1) >> 2;                                             \
        int buf_ = m_ & 1;                                                     \
        float* Aw_ = s_A[1 - ((p) & 1)];                                       \
        if (rank == 0 && tid >= 240 && tid < 272) {                            \
            float v_ = Aw_[tid + PADL];                                        \
            uint32_t ra_ = buf_ ? rh1 : rh0;                                   \
            asm volatile("st.shared::cluster.f32 [%0], %1;"                    \
                         :: "r"(ra_), "f"(v_) : "memory");                     \
        }                                                                      \
        asm volatile("barrier.cluster.arrive.aligned;" ::: "memory");          \
        asm volatile("barrier.cluster.wait.aligned;"   ::: "memory");          \
        if (rank == 1 && tid < 32) Aw_[tid + PADL] = s_mail[buf_][tid];        \
        __syncthreads();                                                       \
    } } while (0)

    // main: 511 full periods (t = 1..2044), then a 3-step tail (2045..2047)
    for (int p = 0; p < 510; p += 2) {
        PERIOD(p,     0, ya0, ya1, ya2, ya3);
        XCHG(p);
        PERIOD(p + 1, 1, yb0, yb1, yb2, yb3);
        XCHG(p + 1);
    }
    PERIOD(510, 0, ya0, ya1, ya2, ya3);   // (510 & 3) == 2 -> no exchange

    // tail period p=511 (H=1): 3 steps, staleness 3 <= OVL-? (lanes>=6 exact)
    {
        const float* __restrict__ Ar = s_A[1];
        float*       __restrict__ Aw = s_A[0];
        float q0 = s_lpt[1][0][cls], q1 = s_lpt[1][1][cls], q2 = s_lpt[1][2][cls];
        float cur = Ar[li];
        float b1v = Ar[li - 1];
        float b2v = Ar[li - 2];
        SUB(q0);
        b1v = __shfl_up_sync(0xffffffffu, cur, 1);
        b2v = __shfl_up_sync(0xffffffffu, cur, 2);
        SUB(q1);
        b1v = __shfl_up_sync(0xffffffffu, cur, 1);
        b2v = __shfl_up_sync(0xffffffffu, cur, 2);
        SUB(q2);
        if (lane >= OVL) Aw[li] = cur;
        __syncthreads();
    }

#undef SUB
#undef PERIOD
#undef XCHG

    // final alpha (t=2047) in s_A[0]; rank1: l=271 -> state 511, l=272 -> 512
    if (rank == 1 && tid == 0) {
        float a = s_A[0][272 + PADL];
        float c = s_A[0][271 + PADL];
        float m = fmaxf(a, c);
        float l2 = m + lg2f_(ex2f_(a - m) + ex2f_(c - m));
        out[b] = -l2 * LN2F;
    }

    // keep both CTAs alive until all remote ops landed
    asm volatile("barrier.cluster.arrive.aligned;" ::: "memory");
    asm volatile("barrier.cluster.wait.aligned;"   ::: "memory");
}

extern "C" void kernel_launch(void* const* d_in, const int* in_sizes, int n_in,
                              void* d_out, int out_size) {
    const int*   y_true;
    const float* y_pred;
    if (in_sizes[0] == CTC_B * CTC_L) {
        y_true = (const int*)d_in[0];
        y_pred = (const float*)d_in[1];
    } else {
        y_true = (const int*)d_in[1];
        y_pred = (const float*)d_in[0];
    }
    float* out = (float*)d_out;

    ctc_forward_kernel<<<2 * CTC_B, NTHR>>>(y_true, y_pred, out);
}